// round 3
// baseline (speedup 1.0000x reference)
#include <cuda_runtime.h>
#include <cuda_bf16.h>
#include <cstdint>

#define TT 128
#define BB 256
#define FF 76
#define HH 64
#define GG 192   // 3*H
#define NHEAD 4
#define DFF 256
#define AH 8

// ---------------- scratch (device globals; no runtime allocation) ----------------
// hs: [F][B][T][H] fp32  = 76*256*128*64 floats (~637 MB)
__device__ float g_hs[(size_t)FF * BB * TT * HH];
// emb: [B][F][H]
__device__ float g_emb[(size_t)BB * FF * HH];

// ---------------- fast activations ----------------
__device__ __forceinline__ float sigmoidf_(float x) {
    return 1.0f / (1.0f + __expf(-x));
}
__device__ __forceinline__ float tanhf_(float x) {
    float e2 = __expf(2.0f * x);
    return (e2 - 1.0f) / (e2 + 1.0f);
}

// =====================================================================
// Kernel A: fused per-feature GRU scan.
// grid (B/64, F), block 256 = 16x16. Each block: one feature f, 64 batches.
// smem: wT [64][193] (W_hh transposed, padded), hT [64(j)][65(b)], w_ih/b_ih/b_hh rows, x staging.
// Thread (tx,ty): batches 4*ty..4*ty+3, hidden units j = tx + 16*m, m=0..3.
// =====================================================================
#define WT_STRIDE 193
#define HT_STRIDE 65
#define SMEM_A_FLOATS (64 * WT_STRIDE + 64 * HT_STRIDE + 3 * GG + 64)

__global__ void __launch_bounds__(256) gru_kernel(
    const float* __restrict__ x,      // (T,B,F)
    const float* __restrict__ w_ih,   // (F,3H)
    const float* __restrict__ w_hh,   // (F,3H,H)
    const float* __restrict__ b_ih,   // (F,3H)
    const float* __restrict__ b_hh)   // (F,3H)
{
    extern __shared__ float sm[];
    float* wT   = sm;                          // 64*193
    float* hT   = wT + 64 * WT_STRIDE;         // 64*65
    float* swih = hT + 64 * HT_STRIDE;         // 192
    float* sbih = swih + GG;                   // 192
    float* sbhh = sbih + GG;                   // 192
    float* sx   = sbhh + GG;                   // 64

    const int f  = blockIdx.y;
    const int b0 = blockIdx.x * 64;
    const int tid = threadIdx.x;
    const int tx = tid & 15, ty = tid >> 4;
    const int bloc = 4 * ty;

    // load + transpose W_hh[f]: wT[k][g] = w_hh[f][g][k]
    const float* whf = w_hh + (size_t)f * GG * HH;
    for (int idx = tid; idx < GG * HH; idx += 256) {
        int g = idx >> 6, k = idx & 63;
        wT[k * WT_STRIDE + g] = whf[idx];
    }
    if (tid < GG) {
        swih[tid] = w_ih[(size_t)f * GG + tid];
        sbih[tid] = b_ih[(size_t)f * GG + tid];
        sbhh[tid] = b_hh[(size_t)f * GG + tid];
    }
    for (int idx = tid; idx < 64 * HT_STRIDE; idx += 256) hT[idx] = 0.0f;
    __syncthreads();

    const size_t hsbase = ((size_t)(f * BB + b0 + bloc)) * TT * HH;

    for (int t = 0; t < TT; ++t) {
        if (tid < 64) sx[tid] = x[(size_t)t * BB * FF + (size_t)(b0 + tid) * FF + f];
        __syncthreads();

        float accR[4][4], accZ[4][4], accN[4][4];
        #pragma unroll
        for (int i = 0; i < 4; ++i)
            #pragma unroll
            for (int m = 0; m < 4; ++m) { accR[i][m] = 0.f; accZ[i][m] = 0.f; accN[i][m] = 0.f; }

        #pragma unroll 4
        for (int k = 0; k < HH; ++k) {
            const float hv0 = hT[k * HT_STRIDE + bloc + 0];
            const float hv1 = hT[k * HT_STRIDE + bloc + 1];
            const float hv2 = hT[k * HT_STRIDE + bloc + 2];
            const float hv3 = hT[k * HT_STRIDE + bloc + 3];
            const float* wrow = wT + k * WT_STRIDE;
            #pragma unroll
            for (int m = 0; m < 4; ++m) {
                const int j = tx + 16 * m;
                const float wr = wrow[j];
                const float wz = wrow[64 + j];
                const float wn = wrow[128 + j];
                accR[0][m] += hv0 * wr; accR[1][m] += hv1 * wr;
                accR[2][m] += hv2 * wr; accR[3][m] += hv3 * wr;
                accZ[0][m] += hv0 * wz; accZ[1][m] += hv1 * wz;
                accZ[2][m] += hv2 * wz; accZ[3][m] += hv3 * wz;
                accN[0][m] += hv0 * wn; accN[1][m] += hv1 * wn;
                accN[2][m] += hv2 * wn; accN[3][m] += hv3 * wn;
            }
        }
        __syncthreads();  // all hT reads done before updates

        #pragma unroll
        for (int m = 0; m < 4; ++m) {
            const int j = tx + 16 * m;
            const float wir = swih[j],       bir = sbih[j],       bhr = sbhh[j];
            const float wiz = swih[64 + j],  biz = sbih[64 + j],  bhz = sbhh[64 + j];
            const float win = swih[128 + j], bin = sbih[128 + j], bhn = sbhh[128 + j];
            #pragma unroll
            for (int i = 0; i < 4; ++i) {
                const float xv = sx[bloc + i];
                const float r = sigmoidf_(xv * wir + bir + accR[i][m] + bhr);
                const float z = sigmoidf_(xv * wiz + biz + accZ[i][m] + bhz);
                const float n = tanhf_(xv * win + bin + r * (accN[i][m] + bhn));
                const float hold = hT[j * HT_STRIDE + bloc + i];
                const float hnew = (1.0f - z) * n + z * hold;
                hT[j * HT_STRIDE + bloc + i] = hnew;
                g_hs[hsbase + (size_t)i * TT * HH + (size_t)t * HH + j] = hnew;
            }
        }
        __syncthreads();  // hT updates visible before next step
    }
}

// =====================================================================
// Kernel B: per-(f,b) time attention (SingleAttention 'new', time-aware).
// grid (B, F), block 128 (= T threads). Reads 32KB h-tile into smem.
// =====================================================================
__global__ void __launch_bounds__(128) attn_kernel(
    const float* __restrict__ att_Wt,   // (F,H,AH)
    const float* __restrict__ att_Wx,   // (F,H,AH)
    const float* __restrict__ att_rate) // (F,)
{
    __shared__ float sh[TT * 65];
    __shared__ float sWt[HH * AH];
    __shared__ float sWx[HH * AH];
    __shared__ float sq[AH];
    __shared__ float sa[TT];
    __shared__ float red[4], red2[4];
    __shared__ float pare[TT];

    const int b = blockIdx.x, f = blockIdx.y;
    const int tid = threadIdx.x;

    const float* hsrc = g_hs + ((size_t)(f * BB + b)) * TT * HH;
    for (int idx = tid; idx < TT * HH; idx += 128)
        sh[(idx >> 6) * 65 + (idx & 63)] = hsrc[idx];
    for (int idx = tid; idx < HH * AH; idx += 128) {
        sWt[idx] = att_Wt[(size_t)f * HH * AH + idx];
        sWx[idx] = att_Wx[(size_t)f * HH * AH + idx];
    }
    __syncthreads();

    if (tid < AH) {
        float q = 0.f;
        for (int j = 0; j < HH; ++j) q += sh[(TT - 1) * 65 + j] * sWt[j * AH + tid];
        sq[tid] = q;
    }
    __syncthreads();

    // each thread owns one time step t = tid
    const int t = tid;
    float kv[AH];
    #pragma unroll
    for (int a = 0; a < AH; ++a) kv[a] = 0.f;
    for (int j = 0; j < HH; ++j) {
        const float hv = sh[t * 65 + j];
        #pragma unroll
        for (int a = 0; a < AH; ++a) kv[a] += hv * sWx[j * AH + a];
    }
    float dp = 0.f;
    #pragma unroll
    for (int a = 0; a < AH; ++a) dp += sq[a] * kv[a];

    const float sig = sigmoidf_(dp);
    const float sr = sigmoidf_(att_rate[f]);
    const float decay = (float)(TT - t);             // arange(T,0,-1)
    const float denom = sr * (__logf(2.72f + (1.0f - sig)) * decay);
    float e = fmaxf(sig / denom, 0.0f);

    // block softmax over 128 threads
    float mval = e;
    #pragma unroll
    for (int o = 16; o > 0; o >>= 1) mval = fmaxf(mval, __shfl_xor_sync(0xffffffffu, mval, o));
    if ((tid & 31) == 0) red[tid >> 5] = mval;
    __syncthreads();
    mval = fmaxf(fmaxf(red[0], red[1]), fmaxf(red[2], red[3]));
    float ex = __expf(e - mval);
    float s = ex;
    #pragma unroll
    for (int o = 16; o > 0; o >>= 1) s += __shfl_xor_sync(0xffffffffu, s, o);
    if ((tid & 31) == 0) red2[tid >> 5] = s;
    __syncthreads();
    s = red2[0] + red2[1] + red2[2] + red2[3];
    sa[t] = ex / s;
    __syncthreads();

    // emb[h] = sum_t a[t]*h[t][h]; 2-way split over t
    const int hidx = tid & 63, part = tid >> 6;
    float acc = 0.f;
    const int t0 = part * 64;
    for (int tt2 = t0; tt2 < t0 + 64; ++tt2) acc += sa[tt2] * sh[tt2 * 65 + hidx];
    pare[tid] = acc;
    __syncthreads();
    if (tid < 64)
        g_emb[((size_t)b * FF + f) * HH + tid] = pare[tid] + pare[tid + 64];
}

// =====================================================================
// Kernel C: per-batch MHA (over F) + FFN + FinalAttentionQKV + output head.
// grid B, block 256, dynamic smem ~120KB.
// =====================================================================
__device__ __forceinline__ void gemm76(const float* __restrict__ sIn,
                                       const float* __restrict__ gW,
                                       const float* __restrict__ gB,
                                       float* __restrict__ sOut,
                                       int tid, bool addTo)
{
    const int j = tid & 63, i0 = tid >> 6;   // i0 in [0,4)
    float acc[19];
    #pragma unroll
    for (int r = 0; r < 19; ++r) acc[r] = 0.f;
    for (int k = 0; k < HH; ++k) {
        const float w = __ldg(&gW[k * HH + j]);
        #pragma unroll
        for (int r = 0; r < 19; ++r) acc[r] += sIn[(i0 + 4 * r) * HH + k] * w;
    }
    const float bj = gB[j];
    #pragma unroll
    for (int r = 0; r < 19; ++r) {
        const int i = i0 + 4 * r;
        float v = acc[r] + bj;
        if (addTo) v += sOut[i * HH + j];
        sOut[i * HH + j] = v;
    }
}

#define SMEM_C_FLOATS (4864 * 5 + 5776)

__global__ void __launch_bounds__(256) mix_kernel(
    const float* __restrict__ wq, const float* __restrict__ bq,
    const float* __restrict__ wk, const float* __restrict__ bk,
    const float* __restrict__ wv, const float* __restrict__ bv,
    const float* __restrict__ wo, const float* __restrict__ bo,
    const float* __restrict__ w1, const float* __restrict__ b1,
    const float* __restrict__ w2, const float* __restrict__ b2,
    const float* __restrict__ fwq, const float* __restrict__ fbq,
    const float* __restrict__ fwk, const float* __restrict__ fbk,
    const float* __restrict__ fwv, const float* __restrict__ fbv,
    const float* __restrict__ o0w, const float* __restrict__ o0b,
    const float* __restrict__ o1w, const float* __restrict__ o1b,
    float* __restrict__ out)
{
    extern __shared__ float sm[];
    float* sE = sm;            // 76*64
    float* sQ = sE + 4864;
    float* sK = sQ + 4864;
    float* sV = sK + 4864;
    float* sC = sV + 4864;
    float* sS = sC + 4864;     // 76*76 scores / later scratch

    const int tid = threadIdx.x;
    const int b = blockIdx.x;

    const float* esrc = g_emb + (size_t)b * FF * HH;
    for (int idx = tid; idx < FF * HH; idx += 256) sE[idx] = esrc[idx];
    __syncthreads();

    // Q, K, V projections
    gemm76(sE, wq, bq, sQ, tid, false);
    gemm76(sE, wk, bk, sK, tid, false);
    gemm76(sE, wv, bv, sV, tid, false);
    __syncthreads();

    // per-head attention over the F axis (dk = 16, scale = 0.25)
    for (int h = 0; h < NHEAD; ++h) {
        const int hd = h * 16;
        for (int idx = tid; idx < FF * FF; idx += 256) {
            const int i = idx / FF, jf = idx % FF;
            float acc = 0.f;
            #pragma unroll
            for (int d = 0; d < 16; ++d) acc += sQ[i * HH + hd + d] * sK[jf * HH + hd + d];
            sS[idx] = acc * 0.25f;
        }
        __syncthreads();
        if (tid < FF) {
            float m = -1e30f;
            for (int jf = 0; jf < FF; ++jf) m = fmaxf(m, sS[tid * FF + jf]);
            float s = 0.f;
            for (int jf = 0; jf < FF; ++jf) { float e = __expf(sS[tid * FF + jf] - m); sS[tid * FF + jf] = e; s += e; }
            const float inv = 1.0f / s;
            for (int jf = 0; jf < FF; ++jf) sS[tid * FF + jf] *= inv;
        }
        __syncthreads();
        for (int idx = tid; idx < FF * 16; idx += 256) {
            const int i = idx / 16, d = idx % 16;
            float acc = 0.f;
            for (int jf = 0; jf < FF; ++jf) acc += sS[i * FF + jf] * sV[jf * HH + hd + d];
            sC[i * HH + hd + d] = acc;
        }
        __syncthreads();
    }

    // output projection + residual into sE
    gemm76(sC, wo, bo, sE, tid, true);
    __syncthreads();

    // FFN: per 8-row chunk, hidden in sH (aliases sC)
    float* sH = sC;
    for (int c = 0; c < 10; ++c) {
        const int r0 = c * 8;
        const int nrows = (FF - r0) < 8 ? (FF - r0) : 8;
        for (int idx = tid; idx < nrows * DFF; idx += 256) {
            const int rr = idx >> 8, jd = idx & 255;
            float acc = b1[jd];
            for (int k = 0; k < HH; ++k) acc += sE[(r0 + rr) * HH + k] * __ldg(&w1[k * DFF + jd]);
            sH[rr * DFF + jd] = fmaxf(acc, 0.0f);
        }
        __syncthreads();
        for (int idx = tid; idx < nrows * HH; idx += 256) {
            const int rr = idx >> 6, j = idx & 63;
            float acc = b2[j];
            for (int kd = 0; kd < DFF; ++kd) acc += sH[rr * DFF + kd] * __ldg(&w2[kd * HH + j]);
            sE[(r0 + rr) * HH + j] += acc;
        }
        __syncthreads();
    }

    // FinalAttentionQKV ('mul')
    float* fqS = sS;          // 64
    float* feS = sS + 64;     // 76
    float* wS  = sS + 192;    // 76
    float* vS  = sS + 320;    // 64
    float* uS  = sS + 448;    // 64
    float* msS = sS + 576;    // 1

    if (tid < HH) {
        float acc = fbq[tid];
        for (int k = 0; k < HH; ++k) acc += sE[(FF - 1) * HH + k] * fwq[k * HH + tid];
        fqS[tid] = acc;
    }
    gemm76(sE, fwk, fbk, sQ, tid, false);   // fk -> sQ
    gemm76(sE, fwv, fbv, sK, tid, false);   // fv -> sK
    __syncthreads();

    if (tid < FF) {
        float acc = 0.f;
        for (int j = 0; j < HH; ++j) acc += sQ[tid * HH + j] * fqS[j];
        feS[tid] = acc;
    }
    __syncthreads();
    if (tid == 0) {
        float m = -1e30f;
        for (int i = 0; i < FF; ++i) m = fmaxf(m, feS[i]);
        float s = 0.f;
        for (int i = 0; i < FF; ++i) { float e = __expf(feS[i] - m); wS[i] = e; s += e; }
        msS[0] = 1.0f / s;
    }
    __syncthreads();
    const float inv = msS[0];
    if (tid < HH) {
        float acc = 0.f;
        for (int i = 0; i < FF; ++i) acc += (wS[i] * inv) * sK[i * HH + tid];
        vS[tid] = acc;
    }
    __syncthreads();
    if (tid < HH) {
        float acc = o0b[tid];
        for (int k = 0; k < HH; ++k) acc += vS[k] * o0w[k * HH + tid];
        uS[tid] = fmaxf(acc, 0.0f);
    }
    __syncthreads();
    if (tid == 0) {
        float acc = o1b[0];
        for (int j = 0; j < HH; ++j) acc += uS[j] * o1w[j];
        out[b] = sigmoidf_(acc);
    }
}

// =====================================================================
extern "C" void kernel_launch(void* const* d_in, const int* in_sizes, int n_in,
                              void* d_out, int out_size)
{
    const float* x     = (const float*)d_in[0];
    const float* wih   = (const float*)d_in[1];
    const float* whh   = (const float*)d_in[2];
    const float* bih   = (const float*)d_in[3];
    const float* bhh   = (const float*)d_in[4];
    const float* aWt   = (const float*)d_in[5];
    const float* aWx   = (const float*)d_in[6];
    const float* arate = (const float*)d_in[7];
    const float* mwq = (const float*)d_in[8],  *mbq = (const float*)d_in[9];
    const float* mwk = (const float*)d_in[10], *mbk = (const float*)d_in[11];
    const float* mwv = (const float*)d_in[12], *mbv = (const float*)d_in[13];
    const float* mwo = (const float*)d_in[14], *mbo = (const float*)d_in[15];
    const float* fw1 = (const float*)d_in[16], *fb1 = (const float*)d_in[17];
    const float* fw2 = (const float*)d_in[18], *fb2 = (const float*)d_in[19];
    const float* fwq = (const float*)d_in[20], *fbq = (const float*)d_in[21];
    const float* fwk = (const float*)d_in[22], *fbk = (const float*)d_in[23];
    const float* fwv = (const float*)d_in[24], *fbv = (const float*)d_in[25];
    const float* o0w = (const float*)d_in[26], *o0b = (const float*)d_in[27];
    const float* o1w = (const float*)d_in[28], *o1b = (const float*)d_in[29];
    float* out = (float*)d_out;

    const int smemA = SMEM_A_FLOATS * 4;
    const int smemC = SMEM_C_FLOATS * 4;
    cudaFuncSetAttribute(gru_kernel, cudaFuncAttributeMaxDynamicSharedMemorySize, smemA);
    cudaFuncSetAttribute(mix_kernel, cudaFuncAttributeMaxDynamicSharedMemorySize, smemC);

    gru_kernel<<<dim3(BB / 64, FF), 256, smemA>>>(x, wih, whh, bih, bhh);
    attn_kernel<<<dim3(BB, FF), 128>>>(aWt, aWx, arate);
    mix_kernel<<<BB, 256, smemC>>>(mwq, mbq, mwk, mbk, mwv, mbv, mwo, mbo,
                                   fw1, fb1, fw2, fb2,
                                   fwq, fbq, fwk, fbk, fwv, fbv,
                                   o0w, o0b, o1w, o1b, out);
}

// round 5
// speedup vs baseline: 1.2001x; 1.2001x over previous
#include <cuda_runtime.h>
#include <cuda_bf16.h>
#include <cstdint>

#define TT 128
#define BB 256
#define FF 76
#define HH 64
#define GG 192   // 3*H
#define NHEAD 4
#define DFF 256
#define AH 8

// ---------------- scratch (device globals; no runtime allocation) ----------------
__device__ float g_hs[(size_t)FF * BB * TT * HH];   // [F][B][T][H]
__device__ float g_emb[(size_t)BB * FF * HH];       // [B][F][H]

// ---------------- helpers ----------------
__device__ __forceinline__ float sigmoidf_(float x) {
    return __fdividef(1.0f, 1.0f + __expf(-x));
}
__device__ __forceinline__ float tanhf_(float x) {
    float e2 = __expf(2.0f * x);
    return __fdividef(e2 - 1.0f, e2 + 1.0f);
}
// packed fp32x2 FMA (SASS FFMA2; PTX-only pattern on Blackwell)
__device__ __forceinline__ unsigned long long ffma2(unsigned long long a,
                                                    unsigned long long b,
                                                    unsigned long long c) {
    unsigned long long d;
    asm("fma.rn.f32x2 %0, %1, %2, %3;" : "=l"(d) : "l"(a), "l"(b), "l"(c));
    return d;
}
__device__ __forceinline__ unsigned long long dup2(float v) {
    float2 p = make_float2(v, v);
    return *(unsigned long long*)&p;
}
__device__ __forceinline__ float2 u2f(unsigned long long u) {
    return *(float2*)&u;
}

// =====================================================================
// Kernel A: fused per-feature GRU scan, f32x2-packed over hidden-unit pairs.
// grid (B/64, F), block 256 = 16x16. Thread (tx,ty): batches 4ty..4ty+3,
// hidden-unit pairs (2tx+32m, 2tx+32m+1), m=0,1.
// smem: wT[64][194] (W_hh^T), hT2[64][65] ull (h duplicated (h,h)), params, x.
// =====================================================================
#define WT_S 194          // float stride (even -> 8B-aligned pairs)
#define HT2_S 65          // ull stride
#define SMEM_A_FLOATS (64 * WT_S + 64 * HT2_S * 2 + 3 * GG + 64)

__global__ void __launch_bounds__(256, 2) gru_kernel(
    const float* __restrict__ x,      // (T,B,F)
    const float* __restrict__ w_ih,   // (F,3H)
    const float* __restrict__ w_hh,   // (F,3H,H)
    const float* __restrict__ b_ih,   // (F,3H)
    const float* __restrict__ b_hh)   // (F,3H)
{
    extern __shared__ float sm[];
    float* wT = sm;                                       // 64*194
    unsigned long long* hT2u = (unsigned long long*)(sm + 64 * WT_S);  // 64*65 ull
    float* swih = sm + 64 * WT_S + 64 * HT2_S * 2;        // 192
    float* sbih = swih + GG;
    float* sbhh = sbih + GG;
    float* sx   = sbhh + GG;                              // 64

    const int f  = blockIdx.y;
    const int b0 = blockIdx.x * 64;
    const int tid = threadIdx.x;
    const int tx = tid & 15, ty = tid >> 4;
    const int bloc = 4 * ty;

    // load + transpose W_hh[f]: wT[k][g] = w_hh[f][g][k]
    const float* whf = w_hh + (size_t)f * GG * HH;
    for (int idx = tid; idx < GG * HH; idx += 256) {
        int g = idx >> 6, k = idx & 63;
        wT[k * WT_S + g] = whf[idx];
    }
    if (tid < GG) {
        swih[tid] = w_ih[(size_t)f * GG + tid];
        sbih[tid] = b_ih[(size_t)f * GG + tid];
        sbhh[tid] = b_hh[(size_t)f * GG + tid];
    }
    for (int idx = tid; idx < 64 * HT2_S; idx += 256) hT2u[idx] = 0ull;
    __syncthreads();

    const size_t hsbase = ((size_t)(f * BB + b0 + bloc)) * TT * HH;

    for (int t = 0; t < TT; ++t) {
        if (tid < 64) sx[tid] = x[(size_t)t * BB * FF + (size_t)(b0 + tid) * FF + f];
        __syncthreads();

        unsigned long long accR[4][2], accZ[4][2], accN[4][2];
        #pragma unroll
        for (int i = 0; i < 4; ++i)
            #pragma unroll
            for (int m = 0; m < 2; ++m) { accR[i][m] = 0ull; accZ[i][m] = 0ull; accN[i][m] = 0ull; }

        #pragma unroll 4
        for (int k = 0; k < HH; ++k) {
            const unsigned long long* hrow = hT2u + (size_t)k * HT2_S + bloc;
            const unsigned long long h0 = hrow[0];
            const unsigned long long h1 = hrow[1];
            const unsigned long long h2 = hrow[2];
            const unsigned long long h3 = hrow[3];
            const float* wrow = wT + k * WT_S + 2 * tx;
            #pragma unroll
            for (int m = 0; m < 2; ++m) {
                const unsigned long long wr = *(const unsigned long long*)(wrow + 32 * m);
                const unsigned long long wz = *(const unsigned long long*)(wrow + 64 + 32 * m);
                const unsigned long long wn = *(const unsigned long long*)(wrow + 128 + 32 * m);
                accR[0][m] = ffma2(wr, h0, accR[0][m]);
                accR[1][m] = ffma2(wr, h1, accR[1][m]);
                accR[2][m] = ffma2(wr, h2, accR[2][m]);
                accR[3][m] = ffma2(wr, h3, accR[3][m]);
                accZ[0][m] = ffma2(wz, h0, accZ[0][m]);
                accZ[1][m] = ffma2(wz, h1, accZ[1][m]);
                accZ[2][m] = ffma2(wz, h2, accZ[2][m]);
                accZ[3][m] = ffma2(wz, h3, accZ[3][m]);
                accN[0][m] = ffma2(wn, h0, accN[0][m]);
                accN[1][m] = ffma2(wn, h1, accN[1][m]);
                accN[2][m] = ffma2(wn, h2, accN[2][m]);
                accN[3][m] = ffma2(wn, h3, accN[3][m]);
            }
        }
        __syncthreads();  // all hT2 reads done before updates

        #pragma unroll
        for (int m = 0; m < 2; ++m) {
            const int j0 = 2 * tx + 32 * m;
            const float2 wir = *(const float2*)&swih[j0];
            const float2 wiz = *(const float2*)&swih[64 + j0];
            const float2 win = *(const float2*)&swih[128 + j0];
            const float2 bir = *(const float2*)&sbih[j0];
            const float2 biz = *(const float2*)&sbih[64 + j0];
            const float2 bin = *(const float2*)&sbih[128 + j0];
            const float2 bhr = *(const float2*)&sbhh[j0];
            const float2 bhz = *(const float2*)&sbhh[64 + j0];
            const float2 bhn = *(const float2*)&sbhh[128 + j0];
            #pragma unroll
            for (int i = 0; i < 4; ++i) {
                const float xv = sx[bloc + i];
                const float2 aR = u2f(accR[i][m]);
                const float2 aZ = u2f(accZ[i][m]);
                const float2 aN = u2f(accN[i][m]);
                const float r0 = sigmoidf_(xv * wir.x + bir.x + aR.x + bhr.x);
                const float r1 = sigmoidf_(xv * wir.y + bir.y + aR.y + bhr.y);
                const float z0 = sigmoidf_(xv * wiz.x + biz.x + aZ.x + bhz.x);
                const float z1 = sigmoidf_(xv * wiz.y + biz.y + aZ.y + bhz.y);
                const float n0 = tanhf_(xv * win.x + bin.x + r0 * (aN.x + bhn.x));
                const float n1 = tanhf_(xv * win.y + bin.y + r1 * (aN.y + bhn.y));
                const float hold0 = ((const float*)&hT2u[(size_t)j0 * HT2_S + bloc + i])[0];
                const float hold1 = ((const float*)&hT2u[(size_t)(j0 + 1) * HT2_S + bloc + i])[0];
                const float h0 = (1.0f - z0) * n0 + z0 * hold0;
                const float h1 = (1.0f - z1) * n1 + z1 * hold1;
                *(float2*)&g_hs[hsbase + (size_t)i * TT * HH + (size_t)t * HH + j0] =
                    make_float2(h0, h1);
                hT2u[(size_t)j0 * HT2_S + bloc + i] = dup2(h0);
                hT2u[(size_t)(j0 + 1) * HT2_S + bloc + i] = dup2(h1);
            }
        }
        __syncthreads();  // updates visible before next step
    }
}

// =====================================================================
// Kernel B: per-(f,b) time attention (SingleAttention 'new', time-aware).
// grid (B, F), block 128 (= T threads).
// =====================================================================
__global__ void __launch_bounds__(128) attn_kernel(
    const float* __restrict__ att_Wt,   // (F,H,AH)
    const float* __restrict__ att_Wx,   // (F,H,AH)
    const float* __restrict__ att_rate) // (F,)
{
    __shared__ float sh[TT * 65];
    __shared__ float sWt[HH * AH];
    __shared__ float sWx[HH * AH];
    __shared__ float sq[AH];
    __shared__ float sa[TT];
    __shared__ float red[4], red2[4];
    __shared__ float pare[TT];

    const int b = blockIdx.x, f = blockIdx.y;
    const int tid = threadIdx.x;

    const float4* hsrc4 = (const float4*)(g_hs + ((size_t)(f * BB + b)) * TT * HH);
    for (int idx = tid; idx < TT * HH / 4; idx += 128) {
        float4 v = hsrc4[idx];
        const int row = idx >> 4;
        float* d = &sh[row * 65 + ((idx & 15) << 2)];
        d[0] = v.x; d[1] = v.y; d[2] = v.z; d[3] = v.w;
    }
    for (int idx = tid; idx < HH * AH; idx += 128) {
        sWt[idx] = att_Wt[(size_t)f * HH * AH + idx];
        sWx[idx] = att_Wx[(size_t)f * HH * AH + idx];
    }
    __syncthreads();

    if (tid < AH) {
        float q = 0.f;
        for (int j = 0; j < HH; ++j) q += sh[(TT - 1) * 65 + j] * sWt[j * AH + tid];
        sq[tid] = q;
    }
    __syncthreads();

    const int t = tid;
    float kv[AH];
    #pragma unroll
    for (int a = 0; a < AH; ++a) kv[a] = 0.f;
    for (int j = 0; j < HH; ++j) {
        const float hv = sh[t * 65 + j];
        #pragma unroll
        for (int a = 0; a < AH; ++a) kv[a] += hv * sWx[j * AH + a];
    }
    float dp = 0.f;
    #pragma unroll
    for (int a = 0; a < AH; ++a) dp += sq[a] * kv[a];

    const float sig = sigmoidf_(dp);
    const float sr = sigmoidf_(att_rate[f]);
    const float decay = (float)(TT - t);
    const float denom = sr * (__logf(2.72f + (1.0f - sig)) * decay);
    float e = fmaxf(__fdividef(sig, denom), 0.0f);

    float mval = e;
    #pragma unroll
    for (int o = 16; o > 0; o >>= 1) mval = fmaxf(mval, __shfl_xor_sync(0xffffffffu, mval, o));
    if ((tid & 31) == 0) red[tid >> 5] = mval;
    __syncthreads();
    mval = fmaxf(fmaxf(red[0], red[1]), fmaxf(red[2], red[3]));
    float ex = __expf(e - mval);
    float s = ex;
    #pragma unroll
    for (int o = 16; o > 0; o >>= 1) s += __shfl_xor_sync(0xffffffffu, s, o);
    if ((tid & 31) == 0) red2[tid >> 5] = s;
    __syncthreads();
    s = red2[0] + red2[1] + red2[2] + red2[3];
    sa[t] = __fdividef(ex, s);
    __syncthreads();

    const int hidx = tid & 63, part = tid >> 6;
    float acc = 0.f;
    const int t0 = part * 64;
    for (int tt2 = t0; tt2 < t0 + 64; ++tt2) acc += sa[tt2] * sh[tt2 * 65 + hidx];
    pare[tid] = acc;
    __syncthreads();
    if (tid < 64)
        g_emb[((size_t)b * FF + f) * HH + tid] = pare[tid] + pare[tid + 64];
}

// =====================================================================
// Kernel C: per-batch MHA (over F) + FFN + FinalAttentionQKV + output head.
// All GEMM weights staged through smem; float2-column GEMM helper.
// =====================================================================
#define RSTRIDE 5120   // 80 rows x 64 (tail rows garbage, stores guarded)

// 76x64 <- (76x64) @ (64x64) with smem weights, optional bias/residual/relu
__device__ __forceinline__ void gemm76s(const float* __restrict__ sIn,
                                        const float* __restrict__ sW,
                                        const float* __restrict__ gB,
                                        float* __restrict__ sOut,
                                        int tid, bool addTo, bool relu)
{
    const int j0 = (tid & 31) * 2;
    const int i0 = tid >> 5;           // 0..7, rows i0 + 8r
    float ax[10], ay[10];
    #pragma unroll
    for (int r = 0; r < 10; ++r) { ax[r] = 0.f; ay[r] = 0.f; }
    for (int k = 0; k < HH; ++k) {
        const float2 w = *(const float2*)&sW[k * 64 + j0];
        #pragma unroll
        for (int r = 0; r < 10; ++r) {
            const float s = sIn[(i0 + 8 * r) * 64 + k];
            ax[r] += s * w.x;
            ay[r] += s * w.y;
        }
    }
    float2 bj = make_float2(0.f, 0.f);
    if (gB) bj = *(const float2*)&gB[j0];
    #pragma unroll
    for (int r = 0; r < 10; ++r) {
        const int i = i0 + 8 * r;
        if (i < FF) {
            float vx = ax[r] + bj.x;
            float vy = ay[r] + bj.y;
            if (addTo) { vx += sOut[i * 64 + j0]; vy += sOut[i * 64 + j0 + 1]; }
            if (relu)  { vx = fmaxf(vx, 0.f);     vy = fmaxf(vy, 0.f); }
            sOut[i * 64 + j0] = vx;
            sOut[i * 64 + j0 + 1] = vy;
        }
    }
}

__device__ __forceinline__ void stageW(const float* __restrict__ g,
                                       float* __restrict__ s, int tid)
{
    const float4* g4 = (const float4*)g;
    float4* s4 = (float4*)s;
    for (int i = tid; i < 1024; i += 256) s4[i] = g4[i];
}

#define SMEM_C_FLOATS (5 * RSTRIDE + 5888 + 4096)

__global__ void __launch_bounds__(256) mix_kernel(
    const float* __restrict__ wq, const float* __restrict__ bq,
    const float* __restrict__ wk, const float* __restrict__ bk,
    const float* __restrict__ wv, const float* __restrict__ bv,
    const float* __restrict__ wo, const float* __restrict__ bo,
    const float* __restrict__ w1, const float* __restrict__ b1,
    const float* __restrict__ w2, const float* __restrict__ b2,
    const float* __restrict__ fwq, const float* __restrict__ fbq,
    const float* __restrict__ fwk, const float* __restrict__ fbk,
    const float* __restrict__ fwv, const float* __restrict__ fbv,
    const float* __restrict__ o0w, const float* __restrict__ o0b,
    const float* __restrict__ o1w, const float* __restrict__ o1b,
    float* __restrict__ out)
{
    extern __shared__ float sm[];
    float* sE = sm;
    float* sQ = sE + RSTRIDE;
    float* sK = sQ + RSTRIDE;
    float* sV = sK + RSTRIDE;
    float* sC = sV + RSTRIDE;
    float* sS = sC + RSTRIDE;   // 5888 (scores 76x76 / W2 chunk staging / scratch)
    float* sW = sS + 5888;      // 4096 weight staging

    const int tid = threadIdx.x;
    const int b = blockIdx.x;

    {
        const float4* esrc = (const float4*)(g_emb + (size_t)b * FF * HH);
        float4* d4 = (float4*)sE;
        for (int idx = tid; idx < FF * HH / 4; idx += 256) d4[idx] = esrc[idx];
    }
    __syncthreads();

    // Q, K, V projections
    stageW(wq, sW, tid); __syncthreads();
    gemm76s(sE, sW, bq, sQ, tid, false, false); __syncthreads();
    stageW(wk, sW, tid); __syncthreads();
    gemm76s(sE, sW, bk, sK, tid, false, false); __syncthreads();
    stageW(wv, sW, tid); __syncthreads();
    gemm76s(sE, sW, bv, sV, tid, false, false); __syncthreads();

    // per-head attention over F (dk=16, scale 0.25)
    for (int h = 0; h < NHEAD; ++h) {
        const int hd = h * 16;
        for (int idx = tid; idx < FF * FF; idx += 256) {
            const int i = idx / FF, jf = idx % FF;
            float acc = 0.f;
            #pragma unroll
            for (int d = 0; d < 16; ++d) acc += sQ[i * HH + hd + d] * sK[jf * HH + hd + d];
            sS[idx] = acc * 0.25f;
        }
        __syncthreads();
        if (tid < FF) {
            float m = -1e30f;
            for (int jf = 0; jf < FF; ++jf) m = fmaxf(m, sS[tid * FF + jf]);
            float s = 0.f;
            for (int jf = 0; jf < FF; ++jf) { float e = __expf(sS[tid * FF + jf] - m); sS[tid * FF + jf] = e; s += e; }
            const float inv = __fdividef(1.0f, s);
            for (int jf = 0; jf < FF; ++jf) sS[tid * FF + jf] *= inv;
        }
        __syncthreads();
        for (int idx = tid; idx < FF * 16; idx += 256) {
            const int i = idx / 16, d = idx % 16;
            float acc = 0.f;
            for (int jf = 0; jf < FF; ++jf) acc += sS[i * FF + jf] * sV[jf * HH + hd + d];
            sC[i * HH + hd + d] = acc;
        }
        __syncthreads();
    }

    // output projection + residual into sE
    stageW(wo, sW, tid); __syncthreads();
    gemm76s(sC, sW, bo, sE, tid, true, false); __syncthreads();

    // FFN: DFF split in 4 chunks of 64; all weights in smem. Accum in sV.
    for (int c = 0; c < 4; ++c) {
        // W1 chunk: sW[k*64+j] = w1[k*256 + 64c + j]
        for (int idx = tid; idx < 4096; idx += 256) {
            const int k = idx >> 6, j = idx & 63;
            sW[idx] = w1[k * DFF + 64 * c + j];
        }
        // W2 chunk: contiguous 4096 floats
        {
            const float4* g4 = (const float4*)(w2 + 4096 * c);
            float4* s4 = (float4*)sS;
            for (int i = tid; i < 1024; i += 256) s4[i] = g4[i];
        }
        __syncthreads();
        gemm76s(sE, sW, b1 + 64 * c, sQ, tid, false, true);   // H chunk (relu)
        __syncthreads();
        gemm76s(sQ, sS, (c == 0) ? b2 : nullptr, sV, tid, c > 0, false);
        __syncthreads();
    }
    for (int idx = tid; idx < FF * HH; idx += 256) sE[idx] += sV[idx];
    __syncthreads();

    // FinalAttentionQKV ('mul')
    float* fqS = sS;          // 64
    float* feS = sS + 64;     // 76
    float* wS  = sS + 192;    // 76
    float* vS  = sS + 320;    // 64
    float* uS  = sS + 448;    // 64
    float* msS = sS + 576;    // 1

    if (tid < HH) {
        float acc = fbq[tid];
        for (int k = 0; k < HH; ++k) acc += sE[(FF - 1) * HH + k] * fwq[k * HH + tid];
        fqS[tid] = acc;
    }
    stageW(fwk, sW, tid); __syncthreads();
    gemm76s(sE, sW, fbk, sQ, tid, false, false); __syncthreads();   // fk -> sQ
    stageW(fwv, sW, tid); __syncthreads();
    gemm76s(sE, sW, fbv, sK, tid, false, false); __syncthreads();   // fv -> sK

    if (tid < FF) {
        float acc = 0.f;
        for (int j = 0; j < HH; ++j) acc += sQ[tid * HH + j] * fqS[j];
        feS[tid] = acc;
    }
    __syncthreads();
    if (tid == 0) {
        float m = -1e30f;
        for (int i = 0; i < FF; ++i) m = fmaxf(m, feS[i]);
        float s = 0.f;
        for (int i = 0; i < FF; ++i) { float e = __expf(feS[i] - m); wS[i] = e; s += e; }
        msS[0] = __fdividef(1.0f, s);
    }
    __syncthreads();
    const float inv = msS[0];
    if (tid < HH) {
        float acc = 0.f;
        for (int i = 0; i < FF; ++i) acc += (wS[i] * inv) * sK[i * HH + tid];
        vS[tid] = acc;
    }
    __syncthreads();
    if (tid < HH) {
        float acc = o0b[tid];
        for (int k = 0; k < HH; ++k) acc += vS[k] * o0w[k * HH + tid];
        uS[tid] = fmaxf(acc, 0.0f);
    }
    __syncthreads();
    if (tid == 0) {
        float acc = o1b[0];
        for (int j = 0; j < HH; ++j) acc += uS[j] * o1w[j];
        out[b] = sigmoidf_(acc);
    }
}

// =====================================================================
extern "C" void kernel_launch(void* const* d_in, const int* in_sizes, int n_in,
                              void* d_out, int out_size)
{
    const float* x     = (const float*)d_in[0];
    const float* wih   = (const float*)d_in[1];
    const float* whh   = (const float*)d_in[2];
    const float* bih   = (const float*)d_in[3];
    const float* bhh   = (const float*)d_in[4];
    const float* aWt   = (const float*)d_in[5];
    const float* aWx   = (const float*)d_in[6];
    const float* arate = (const float*)d_in[7];
    const float* mwq = (const float*)d_in[8],  *mbq = (const float*)d_in[9];
    const float* mwk = (const float*)d_in[10], *mbk = (const float*)d_in[11];
    const float* mwv = (const float*)d_in[12], *mbv = (const float*)d_in[13];
    const float* mwo = (const float*)d_in[14], *mbo = (const float*)d_in[15];
    const float* fw1 = (const float*)d_in[16], *fb1 = (const float*)d_in[17];
    const float* fw2 = (const float*)d_in[18], *fb2 = (const float*)d_in[19];
    const float* fwq = (const float*)d_in[20], *fbq = (const float*)d_in[21];
    const float* fwk = (const float*)d_in[22], *fbk = (const float*)d_in[23];
    const float* fwv = (const float*)d_in[24], *fbv = (const float*)d_in[25];
    const float* o0w = (const float*)d_in[26], *o0b = (const float*)d_in[27];
    const float* o1w = (const float*)d_in[28], *o1b = (const float*)d_in[29];
    float* out = (float*)d_out;

    const int smemA = SMEM_A_FLOATS * 4;
    const int smemC = SMEM_C_FLOATS * 4;
    cudaFuncSetAttribute(gru_kernel, cudaFuncAttributeMaxDynamicSharedMemorySize, smemA);
    cudaFuncSetAttribute(mix_kernel, cudaFuncAttributeMaxDynamicSharedMemorySize, smemC);

    gru_kernel<<<dim3(BB / 64, FF), 256, smemA>>>(x, wih, whh, bih, bhh);
    attn_kernel<<<dim3(BB, FF), 128>>>(aWt, aWx, arate);
    mix_kernel<<<BB, 256, smemC>>>(mwq, mbq, mwk, mbk, mwv, mbv, mwo, mbo,
                                   fw1, fb1, fw2, fb2,
                                   fwq, fbq, fwk, fbk, fwv, fbv,
                                   o0w, o0b, o1w, o1b, out);
}

// round 6
// speedup vs baseline: 1.2566x; 1.0471x over previous
#include <cuda_runtime.h>
#include <cuda_bf16.h>
#include <cstdint>

#define TT 128
#define BB 256
#define FF 76
#define HH 64
#define GG 192   // 3*H
#define NHEAD 4
#define DFF 256
#define AH 8

// ---------------- scratch (device globals; no runtime allocation) ----------------
__device__ float g_hs[(size_t)FF * BB * TT * HH];   // [F][B][T][H]
__device__ float g_emb[(size_t)BB * FF * HH];       // [B][F][H]

// ---------------- helpers ----------------
__device__ __forceinline__ float sigmoidf_(float x) {
    return __fdividef(1.0f, 1.0f + __expf(-x));
}
__device__ __forceinline__ float tanhf_(float x) {
    float e2 = __expf(2.0f * x);
    return __fdividef(e2 - 1.0f, e2 + 1.0f);
}
__device__ __forceinline__ unsigned long long ffma2(unsigned long long a,
                                                    unsigned long long b,
                                                    unsigned long long c) {
    unsigned long long d;
    asm("fma.rn.f32x2 %0, %1, %2, %3;" : "=l"(d) : "l"(a), "l"(b), "l"(c));
    return d;
}
__device__ __forceinline__ unsigned long long dup2(float v) {
    float2 p = make_float2(v, v);
    return *(unsigned long long*)&p;
}
__device__ __forceinline__ float2 u2f(unsigned long long u) {
    return *(float2*)&u;
}

// =====================================================================
// Kernel A: fused per-feature GRU scan, f32x2 over hidden pairs,
// 8 batches per thread to amortize weight LDS.
// grid (4, F), block 128 = 16x8. Thread (tx,ty): batches 8ty..8ty+7,
// hidden pairs (2tx+32m, 2tx+32m+1), m=0,1.
// =====================================================================
#define WT_S 194          // float stride (even -> 8B-aligned pairs)
#define HT2_S 65          // ull stride
#define SMEM_A_FLOATS (64 * WT_S + 64 * HT2_S * 2 + 3 * GG + 32 * 64)

__global__ void __launch_bounds__(128, 2) gru_kernel(
    const float* __restrict__ x,      // (T,B,F)
    const float* __restrict__ w_ih,   // (F,3H)
    const float* __restrict__ w_hh,   // (F,3H,H)
    const float* __restrict__ b_ih,   // (F,3H)
    const float* __restrict__ b_hh)   // (F,3H)
{
    extern __shared__ float sm[];
    float* wT = sm;                                                  // 64*194
    unsigned long long* hT2u = (unsigned long long*)(sm + 64 * WT_S); // 64*65 ull
    float* swih = sm + 64 * WT_S + 64 * HT2_S * 2;                   // 192
    float* sbih = swih + GG;
    float* sbhh = sbih + GG;
    float* sxc  = sbhh + GG;                                         // 32*64 x chunk

    const int f  = blockIdx.y;
    const int b0 = blockIdx.x * 64;
    const int tid = threadIdx.x;
    const int tx = tid & 15, ty = tid >> 4;
    const int bloc = 8 * ty;

    // load + transpose W_hh[f]: wT[k][g] = w_hh[f][g][k]
    const float* whf = w_hh + (size_t)f * GG * HH;
    for (int idx = tid; idx < GG * HH; idx += 128) {
        int g = idx >> 6, k = idx & 63;
        wT[k * WT_S + g] = whf[idx];
    }
    for (int idx = tid; idx < GG; idx += 128) {
        swih[idx] = w_ih[(size_t)f * GG + idx];
        sbih[idx] = b_ih[(size_t)f * GG + idx];
        sbhh[idx] = b_hh[(size_t)f * GG + idx];
    }
    for (int idx = tid; idx < 64 * HT2_S; idx += 128) hT2u[idx] = 0ull;
    __syncthreads();

    const size_t hsbase = ((size_t)(f * BB + b0 + bloc)) * TT * HH;

    // h_prev for this thread's own (j0/j0+1, batch) cells: [m][i] pairs
    float hp0[2][8], hp1[2][8];
    #pragma unroll
    for (int m = 0; m < 2; ++m)
        #pragma unroll
        for (int i = 0; i < 8; ++i) { hp0[m][i] = 0.f; hp1[m][i] = 0.f; }

    for (int tc = 0; tc < 4; ++tc) {
        // stage x chunk: 32 t-steps x 64 batches
        for (int idx = tid; idx < 32 * 64; idx += 128) {
            const int tt = idx >> 6, bb = idx & 63;
            sxc[idx] = x[(size_t)(tc * 32 + tt) * BB * FF + (size_t)(b0 + bb) * FF + f];
        }
        __syncthreads();

        for (int tl = 0; tl < 32; ++tl) {
            const int t = tc * 32 + tl;

            unsigned long long accR[8][2], accZ[8][2], accN[8][2];
            #pragma unroll
            for (int i = 0; i < 8; ++i)
                #pragma unroll
                for (int m = 0; m < 2; ++m) { accR[i][m] = 0ull; accZ[i][m] = 0ull; accN[i][m] = 0ull; }

            #pragma unroll 4
            for (int k = 0; k < HH; ++k) {
                const unsigned long long* hrow = hT2u + (size_t)k * HT2_S + bloc;
                unsigned long long hv[8];
                #pragma unroll
                for (int i = 0; i < 8; ++i) hv[i] = hrow[i];
                const float* wrow = wT + k * WT_S + 2 * tx;
                #pragma unroll
                for (int m = 0; m < 2; ++m) {
                    const unsigned long long wr = *(const unsigned long long*)(wrow + 32 * m);
                    const unsigned long long wz = *(const unsigned long long*)(wrow + 64 + 32 * m);
                    const unsigned long long wn = *(const unsigned long long*)(wrow + 128 + 32 * m);
                    #pragma unroll
                    for (int i = 0; i < 8; ++i) {
                        accR[i][m] = ffma2(wr, hv[i], accR[i][m]);
                        accZ[i][m] = ffma2(wz, hv[i], accZ[i][m]);
                        accN[i][m] = ffma2(wn, hv[i], accN[i][m]);
                    }
                }
            }
            __syncthreads();  // hT2 reads done before updates

            #pragma unroll
            for (int m = 0; m < 2; ++m) {
                const int j0 = 2 * tx + 32 * m;
                const float2 wir = *(const float2*)&swih[j0];
                const float2 wiz = *(const float2*)&swih[64 + j0];
                const float2 win = *(const float2*)&swih[128 + j0];
                const float2 bir = *(const float2*)&sbih[j0];
                const float2 biz = *(const float2*)&sbih[64 + j0];
                const float2 bin = *(const float2*)&sbih[128 + j0];
                const float2 bhr = *(const float2*)&sbhh[j0];
                const float2 bhz = *(const float2*)&sbhh[64 + j0];
                const float2 bhn = *(const float2*)&sbhh[128 + j0];
                #pragma unroll
                for (int i = 0; i < 8; ++i) {
                    const float xv = sxc[tl * 64 + bloc + i];
                    const float2 aR = u2f(accR[i][m]);
                    const float2 aZ = u2f(accZ[i][m]);
                    const float2 aN = u2f(accN[i][m]);
                    const float r0 = sigmoidf_(xv * wir.x + bir.x + aR.x + bhr.x);
                    const float r1 = sigmoidf_(xv * wir.y + bir.y + aR.y + bhr.y);
                    const float z0 = sigmoidf_(xv * wiz.x + biz.x + aZ.x + bhz.x);
                    const float z1 = sigmoidf_(xv * wiz.y + biz.y + aZ.y + bhz.y);
                    const float n0 = tanhf_(xv * win.x + bin.x + r0 * (aN.x + bhn.x));
                    const float n1 = tanhf_(xv * win.y + bin.y + r1 * (aN.y + bhn.y));
                    const float h0 = (1.0f - z0) * n0 + z0 * hp0[m][i];
                    const float h1 = (1.0f - z1) * n1 + z1 * hp1[m][i];
                    hp0[m][i] = h0; hp1[m][i] = h1;
                    *(float2*)&g_hs[hsbase + (size_t)i * TT * HH + (size_t)t * HH + j0] =
                        make_float2(h0, h1);
                    hT2u[(size_t)j0 * HT2_S + bloc + i] = dup2(h0);
                    hT2u[(size_t)(j0 + 1) * HT2_S + bloc + i] = dup2(h1);
                }
            }
            __syncthreads();  // updates visible before next step / chunk reload
        }
    }
}

// =====================================================================
// Kernel B: per-(f,b) time attention (SingleAttention 'new', time-aware).
// grid (B, F), block 128.
// =====================================================================
__global__ void __launch_bounds__(128) attn_kernel(
    const float* __restrict__ att_Wt,   // (F,H,AH)
    const float* __restrict__ att_Wx,   // (F,H,AH)
    const float* __restrict__ att_rate) // (F,)
{
    __shared__ float sh[TT * 65];
    __shared__ float sWt[HH * AH];
    __shared__ float sWx[HH * AH];
    __shared__ float sq[AH];
    __shared__ float sa[TT];
    __shared__ float red[4], red2[4];
    __shared__ float pare[TT];

    const int b = blockIdx.x, f = blockIdx.y;
    const int tid = threadIdx.x;

    const float4* hsrc4 = (const float4*)(g_hs + ((size_t)(f * BB + b)) * TT * HH);
    for (int idx = tid; idx < TT * HH / 4; idx += 128) {
        float4 v = hsrc4[idx];
        const int row = idx >> 4;
        float* d = &sh[row * 65 + ((idx & 15) << 2)];
        d[0] = v.x; d[1] = v.y; d[2] = v.z; d[3] = v.w;
    }
    for (int idx = tid; idx < HH * AH; idx += 128) {
        sWt[idx] = att_Wt[(size_t)f * HH * AH + idx];
        sWx[idx] = att_Wx[(size_t)f * HH * AH + idx];
    }
    __syncthreads();

    if (tid < AH) {
        float q = 0.f;
        for (int j = 0; j < HH; ++j) q += sh[(TT - 1) * 65 + j] * sWt[j * AH + tid];
        sq[tid] = q;
    }
    __syncthreads();

    const int t = tid;
    float kv[AH];
    #pragma unroll
    for (int a = 0; a < AH; ++a) kv[a] = 0.f;
    for (int j = 0; j < HH; ++j) {
        const float hv = sh[t * 65 + j];
        #pragma unroll
        for (int a = 0; a < AH; ++a) kv[a] += hv * sWx[j * AH + a];
    }
    float dp = 0.f;
    #pragma unroll
    for (int a = 0; a < AH; ++a) dp += sq[a] * kv[a];

    const float sig = sigmoidf_(dp);
    const float sr = sigmoidf_(att_rate[f]);
    const float decay = (float)(TT - t);
    const float denom = sr * (__logf(2.72f + (1.0f - sig)) * decay);
    float e = fmaxf(__fdividef(sig, denom), 0.0f);

    float mval = e;
    #pragma unroll
    for (int o = 16; o > 0; o >>= 1) mval = fmaxf(mval, __shfl_xor_sync(0xffffffffu, mval, o));
    if ((tid & 31) == 0) red[tid >> 5] = mval;
    __syncthreads();
    mval = fmaxf(fmaxf(red[0], red[1]), fmaxf(red[2], red[3]));
    float ex = __expf(e - mval);
    float s = ex;
    #pragma unroll
    for (int o = 16; o > 0; o >>= 1) s += __shfl_xor_sync(0xffffffffu, s, o);
    if ((tid & 31) == 0) red2[tid >> 5] = s;
    __syncthreads();
    s = red2[0] + red2[1] + red2[2] + red2[3];
    sa[t] = __fdividef(ex, s);
    __syncthreads();

    const int hidx = tid & 63, part = tid >> 6;
    float acc = 0.f;
    const int t0 = part * 64;
    for (int tt2 = t0; tt2 < t0 + 64; ++tt2) acc += sa[tt2] * sh[tt2 * 65 + hidx];
    pare[tid] = acc;
    __syncthreads();
    if (tid < 64)
        g_emb[((size_t)b * FF + f) * HH + tid] = pare[tid] + pare[tid + 64];
}

// =====================================================================
// Kernel C: per-batch MHA + FFN + FinalAttention + head.
// smem cut to ~101KB (4 tile buffers + 1 scratch) -> 2 blocks/SM.
// =====================================================================
#define BUFSZ 4864   // 76*64

__device__ __forceinline__ void gemm76s(const float* __restrict__ sIn,
                                        const float* __restrict__ sW,
                                        const float* __restrict__ gB,
                                        float* __restrict__ sOut,
                                        int tid, bool addTo, bool relu)
{
    const int j0 = (tid & 31) * 2;
    const int i0 = tid >> 5;           // 0..7, rows i0 + 8r
    float ax[10], ay[10];
    #pragma unroll
    for (int r = 0; r < 10; ++r) { ax[r] = 0.f; ay[r] = 0.f; }
    for (int k = 0; k < HH; ++k) {
        const float2 w = *(const float2*)&sW[k * 64 + j0];
        #pragma unroll
        for (int r = 0; r < 10; ++r) {
            const float s = sIn[(i0 + 8 * r) * 64 + k];
            ax[r] += s * w.x;
            ay[r] += s * w.y;
        }
    }
    float2 bj = make_float2(0.f, 0.f);
    if (gB) bj = *(const float2*)&gB[j0];
    #pragma unroll
    for (int r = 0; r < 10; ++r) {
        const int i = i0 + 8 * r;
        if (i < FF) {
            float vx = ax[r] + bj.x;
            float vy = ay[r] + bj.y;
            if (addTo) { vx += sOut[i * 64 + j0]; vy += sOut[i * 64 + j0 + 1]; }
            if (relu)  { vx = fmaxf(vx, 0.f);     vy = fmaxf(vy, 0.f); }
            sOut[i * 64 + j0] = vx;
            sOut[i * 64 + j0 + 1] = vy;
        }
    }
}

__device__ __forceinline__ void stageW(const float* __restrict__ g,
                                       float* __restrict__ s, int tid)
{
    const float4* g4 = (const float4*)g;
    float4* s4 = (float4*)s;
    for (int i = tid; i < 1024; i += 256) s4[i] = g4[i];
}

#define SMEM_C_FLOATS (4 * BUFSZ + 5888)

__global__ void __launch_bounds__(256) mix_kernel(
    const float* __restrict__ wq, const float* __restrict__ bq,
    const float* __restrict__ wk, const float* __restrict__ bk,
    const float* __restrict__ wv, const float* __restrict__ bv,
    const float* __restrict__ wo, const float* __restrict__ bo,
    const float* __restrict__ w1, const float* __restrict__ b1,
    const float* __restrict__ w2, const float* __restrict__ b2,
    const float* __restrict__ fwq, const float* __restrict__ fbq,
    const float* __restrict__ fwk, const float* __restrict__ fbk,
    const float* __restrict__ fwv, const float* __restrict__ fbv,
    const float* __restrict__ o0w, const float* __restrict__ o0b,
    const float* __restrict__ o1w, const float* __restrict__ o1b,
    float* __restrict__ out)
{
    extern __shared__ float sm[];
    float* sE = sm;                 // emb / residual stream
    float* sQ = sE + BUFSZ;         // Q -> ctx (in-place) -> ffn hidden -> fk
    float* sK = sQ + BUFSZ;         // K -> W2 staging -> fv
    float* sV = sK + BUFSZ;         // V -> ffn accum
    float* sS = sV + BUFSZ;         // 5888: weight staging / scores / scratch

    const int tid = threadIdx.x;
    const int b = blockIdx.x;

    {
        const float4* esrc = (const float4*)(g_emb + (size_t)b * FF * HH);
        float4* d4 = (float4*)sE;
        for (int idx = tid; idx < FF * HH / 4; idx += 256) d4[idx] = esrc[idx];
    }
    __syncthreads();

    // Q, K, V projections (weights staged through sS)
    stageW(wq, sS, tid); __syncthreads();
    gemm76s(sE, sS, bq, sQ, tid, false, false); __syncthreads();
    stageW(wk, sS, tid); __syncthreads();
    gemm76s(sE, sS, bk, sK, tid, false, false); __syncthreads();
    stageW(wv, sS, tid); __syncthreads();
    gemm76s(sE, sS, bv, sV, tid, false, false); __syncthreads();

    // per-head attention over F (dk=16, scale 0.25); ctx overwrites sQ's head cols
    for (int h = 0; h < NHEAD; ++h) {
        const int hd = h * 16;
        for (int idx = tid; idx < FF * FF; idx += 256) {
            const int i = idx / FF, jf = idx % FF;
            float acc = 0.f;
            #pragma unroll
            for (int d = 0; d < 16; ++d) acc += sQ[i * HH + hd + d] * sK[jf * HH + hd + d];
            sS[idx] = acc * 0.25f;
        }
        __syncthreads();
        if (tid < FF) {
            float m = -1e30f;
            for (int jf = 0; jf < FF; ++jf) m = fmaxf(m, sS[tid * FF + jf]);
            float s = 0.f;
            for (int jf = 0; jf < FF; ++jf) { float e = __expf(sS[tid * FF + jf] - m); sS[tid * FF + jf] = e; s += e; }
            const float inv = __fdividef(1.0f, s);
            for (int jf = 0; jf < FF; ++jf) sS[tid * FF + jf] *= inv;
        }
        __syncthreads();
        for (int idx = tid; idx < FF * 16; idx += 256) {
            const int i = idx / 16, d = idx % 16;
            float acc = 0.f;
            for (int jf = 0; jf < FF; ++jf) acc += sS[i * FF + jf] * sV[jf * HH + hd + d];
            sQ[i * HH + hd + d] = acc;   // in-place: Q cols for this head are dead
        }
        __syncthreads();
    }

    // output projection + residual into sE
    stageW(wo, sS, tid); __syncthreads();
    gemm76s(sQ, sS, bo, sE, tid, true, false); __syncthreads();

    // FFN: DFF in 4 chunks of 64; W1 chunk in sS, W2 chunk in sK; accum in sV
    for (int c = 0; c < 4; ++c) {
        for (int idx = tid; idx < 4096; idx += 256) {
            const int k = idx >> 6, j = idx & 63;
            sS[idx] = w1[k * DFF + 64 * c + j];
        }
        {
            const float4* g4 = (const float4*)(w2 + 4096 * c);
            float4* s4 = (float4*)sK;
            for (int i = tid; i < 1024; i += 256) s4[i] = g4[i];
        }
        __syncthreads();
        gemm76s(sE, sS, b1 + 64 * c, sQ, tid, false, true);
        __syncthreads();
        gemm76s(sQ, sK, (c == 0) ? b2 : nullptr, sV, tid, c > 0, false);
        __syncthreads();
    }
    for (int idx = tid; idx < FF * HH; idx += 256) sE[idx] += sV[idx];
    __syncthreads();

    // FinalAttentionQKV ('mul'); scratch lives past the 4096-float staging area
    float* fqS = sS + 4608;   // 64
    float* feS = sS + 4672;   // 76
    float* wS  = sS + 4768;   // 76
    float* vS  = sS + 4848;   // 64
    float* uS  = sS + 4912;   // 64
    float* msS = sS + 4976;   // 1

    if (tid < HH) {
        float acc = fbq[tid];
        for (int k = 0; k < HH; ++k) acc += sE[(FF - 1) * HH + k] * fwq[k * HH + tid];
        fqS[tid] = acc;
    }
    stageW(fwk, sS, tid); __syncthreads();
    gemm76s(sE, sS, fbk, sQ, tid, false, false); __syncthreads();   // fk -> sQ
    stageW(fwv, sS, tid); __syncthreads();
    gemm76s(sE, sS, fbv, sK, tid, false, false); __syncthreads();   // fv -> sK

    if (tid < FF) {
        float acc = 0.f;
        for (int j = 0; j < HH; ++j) acc += sQ[tid * HH + j] * fqS[j];
        feS[tid] = acc;
    }
    __syncthreads();
    if (tid == 0) {
        float m = -1e30f;
        for (int i = 0; i < FF; ++i) m = fmaxf(m, feS[i]);
        float s = 0.f;
        for (int i = 0; i < FF; ++i) { float e = __expf(feS[i] - m); wS[i] = e; s += e; }
        msS[0] = __fdividef(1.0f, s);
    }
    __syncthreads();
    const float inv = msS[0];
    if (tid < HH) {
        float acc = 0.f;
        for (int i = 0; i < FF; ++i) acc += (wS[i] * inv) * sK[i * HH + tid];
        vS[tid] = acc;
    }
    __syncthreads();
    if (tid < HH) {
        float acc = o0b[tid];
        for (int k = 0; k < HH; ++k) acc += vS[k] * o0w[k * HH + tid];
        uS[tid] = fmaxf(acc, 0.0f);
    }
    __syncthreads();
    if (tid == 0) {
        float acc = o1b[0];
        for (int j = 0; j < HH; ++j) acc += uS[j] * o1w[j];
        out[b] = sigmoidf_(acc);
    }
}

// =====================================================================
extern "C" void kernel_launch(void* const* d_in, const int* in_sizes, int n_in,
                              void* d_out, int out_size)
{
    const float* x     = (const float*)d_in[0];
    const float* wih   = (const float*)d_in[1];
    const float* whh   = (const float*)d_in[2];
    const float* bih   = (const float*)d_in[3];
    const float* bhh   = (const float*)d_in[4];
    const float* aWt   = (const float*)d_in[5];
    const float* aWx   = (const float*)d_in[6];
    const float* arate = (const float*)d_in[7];
    const float* mwq = (const float*)d_in[8],  *mbq = (const float*)d_in[9];
    const float* mwk = (const float*)d_in[10], *mbk = (const float*)d_in[11];
    const float* mwv = (const float*)d_in[12], *mbv = (const float*)d_in[13];
    const float* mwo = (const float*)d_in[14], *mbo = (const float*)d_in[15];
    const float* fw1 = (const float*)d_in[16], *fb1 = (const float*)d_in[17];
    const float* fw2 = (const float*)d_in[18], *fb2 = (const float*)d_in[19];
    const float* fwq = (const float*)d_in[20], *fbq = (const float*)d_in[21];
    const float* fwk = (const float*)d_in[22], *fbk = (const float*)d_in[23];
    const float* fwv = (const float*)d_in[24], *fbv = (const float*)d_in[25];
    const float* o0w = (const float*)d_in[26], *o0b = (const float*)d_in[27];
    const float* o1w = (const float*)d_in[28], *o1b = (const float*)d_in[29];
    float* out = (float*)d_out;

    const int smemA = SMEM_A_FLOATS * 4;
    const int smemC = SMEM_C_FLOATS * 4;
    cudaFuncSetAttribute(gru_kernel, cudaFuncAttributeMaxDynamicSharedMemorySize, smemA);
    cudaFuncSetAttribute(mix_kernel, cudaFuncAttributeMaxDynamicSharedMemorySize, smemC);

    gru_kernel<<<dim3(BB / 64, FF), 128, smemA>>>(x, wih, whh, bih, bhh);
    attn_kernel<<<dim3(BB, FF), 128>>>(aWt, aWx, arate);
    mix_kernel<<<BB, 256, smemC>>>(mwq, mbq, mwk, mbk, mwv, mbv, mwo, mbo,
                                   fw1, fb1, fw2, fb2,
                                   fwq, fbq, fwk, fbk, fwv, fbv,
                                   o0w, o0b, o1w, o1b, out);
}

// round 7
// speedup vs baseline: 1.5509x; 1.2342x over previous
#include <cuda_runtime.h>
#include <cuda_bf16.h>
#include <cstdint>

#define TT 128
#define BB 256
#define FF 76
#define HH 64
#define GG 192   // 3*H
#define NHEAD 4
#define DFF 256
#define AH 8

// ---------------- scratch (device globals; no runtime allocation) ----------------
__device__ float g_hs[(size_t)FF * BB * TT * HH];   // [F][B][T][H]
__device__ float g_emb[(size_t)BB * FF * HH];       // [B][F][H]

// ---------------- helpers ----------------
__device__ __forceinline__ float sigmoidf_(float x) {
    return __fdividef(1.0f, 1.0f + __expf(-x));
}
__device__ __forceinline__ float tanh_ap(float x) {
    float y;
    asm("tanh.approx.f32 %0, %1;" : "=f"(y) : "f"(x));
    return y;
}
__device__ __forceinline__ unsigned long long ffma2(unsigned long long a,
                                                    unsigned long long b,
                                                    unsigned long long c) {
    unsigned long long d;
    asm("fma.rn.f32x2 %0, %1, %2, %3;" : "=l"(d) : "l"(a), "l"(b), "l"(c));
    return d;
}
__device__ __forceinline__ unsigned long long dup2(float v) {
    unsigned long long d;
    asm("mov.b64 %0, {%1, %1};" : "=l"(d) : "f"(v));
    return d;
}
__device__ __forceinline__ float2 u2f(unsigned long long u) {
    return *(float2*)&u;
}

// =====================================================================
// Kernel A: fused per-feature GRU scan.
// f32x2 lanes = adjacent BATCH pair. grid (8, F) = 608 blocks, block 128,
// 3 blocks/SM. Thread (tx 0-31, ty 0-3): hidden j = 2tx, 2tx+1; batches
// 8ty..8ty+7 (4 pairs). h double-buffered scalar [k][b] -> 1 barrier per t.
// r,z weight rows pre-scaled by 0.5 so sigmoid = 0.5*tanh(acc)+0.5.
// =====================================================================
#define WT_S 194          // wT row stride (floats)
#define HT_S 34           // h row stride (floats, even)
#define XCH 32            // t-chunk
#define SMEM_A_FLOATS (64 * WT_S + 2 * 64 * HT_S + GG + 128 + 64 + 64 + XCH * 32)

__global__ void __launch_bounds__(128, 3) gru_kernel(
    const float* __restrict__ x,      // (T,B,F)
    const float* __restrict__ w_ih,   // (F,3H)
    const float* __restrict__ w_hh,   // (F,3H,H)
    const float* __restrict__ b_ih,   // (F,3H)
    const float* __restrict__ b_hh)   // (F,3H)
{
    extern __shared__ float sm[];
    float* wT   = sm;                          // [64][194]: wT[k][g] = w_hh[f][g][k] (*0.5 for g<128)
    float* hbuf = wT + 64 * WT_S;              // 2 x [64][34]
    float* swih = hbuf + 2 * 64 * HT_S;        // 192 (*0.5 for first 128)
    float* sbrz = swih + GG;                   // 128: 0.5*(b_ih+b_hh) for r,z
    float* sbin = sbrz + 128;                  // 64: b_ih n-gate
    float* sbhn = sbin + 64;                   // 64: b_hh n-gate
    float* sxc  = sbhn + 64;                   // XCH*32

    const int f  = blockIdx.y;
    const int b0 = blockIdx.x * 32;
    const int tid = threadIdx.x;
    const int tx = tid & 31, ty = tid >> 5;
    const int j0 = 2 * tx;
    const int bloc = 8 * ty;

    // stage + transpose W_hh[f] (r,z rows pre-halved)
    const float* whf = w_hh + (size_t)f * GG * HH;
    for (int idx = tid; idx < GG * HH; idx += 128) {
        const int g = idx >> 6, k = idx & 63;
        const float s = (g < 128) ? 0.5f : 1.0f;
        wT[k * WT_S + g] = whf[idx] * s;
    }
    for (int idx = tid; idx < GG; idx += 128) {
        const float s = (idx < 128) ? 0.5f : 1.0f;
        swih[idx] = w_ih[(size_t)f * GG + idx] * s;
    }
    if (tid < 128) sbrz[tid] = 0.5f * (b_ih[(size_t)f * GG + tid] + b_hh[(size_t)f * GG + tid]);
    if (tid < 64) {
        sbin[tid] = b_ih[(size_t)f * GG + 128 + tid];
        sbhn[tid] = b_hh[(size_t)f * GG + 128 + tid];
    }
    for (int idx = tid; idx < 2 * 64 * HT_S; idx += 128) hbuf[idx] = 0.0f;
    __syncthreads();

    // per-thread constants (hoisted)
    const float wir0 = swih[j0],       wir1 = swih[j0 + 1];
    const float wiz0 = swih[64 + j0],  wiz1 = swih[64 + j0 + 1];
    const float win0 = swih[128 + j0], win1 = swih[128 + j0 + 1];
    const float br0 = sbrz[j0],      br1 = sbrz[j0 + 1];
    const float bz0 = sbrz[64 + j0], bz1 = sbrz[64 + j0 + 1];
    const float bn0 = sbin[j0],      bn1 = sbin[j0 + 1];
    const float bh0 = sbhn[j0],      bh1 = sbhn[j0 + 1];

    // h_prev for this thread's cells: [j][pair] = (batch even, batch odd)
    float2 hp[2][4];
    #pragma unroll
    for (int jj = 0; jj < 2; ++jj)
        #pragma unroll
        for (int p = 0; p < 4; ++p) hp[jj][p] = make_float2(0.f, 0.f);

    const size_t gbase0 = ((size_t)f * BB + b0 + bloc) * TT * HH + j0;

    for (int tc = 0; tc < TT / XCH; ++tc) {
        // stage x chunk: XCH steps x 32 batches
        for (int idx = tid; idx < XCH * 32; idx += 128) {
            const int tt = idx >> 5, bb = idx & 31;
            sxc[idx] = x[(size_t)(tc * XCH + tt) * BB * FF + (size_t)(b0 + bb) * FF + f];
        }
        __syncthreads();

        for (int tl = 0; tl < XCH; ++tl) {
            const int t = tc * XCH + tl;
            const float* hc = hbuf + (t & 1) * 64 * HT_S;
            float* hn = hbuf + ((t & 1) ^ 1) * 64 * HT_S;

            unsigned long long accR[2][4], accZ[2][4], accN[2][4];
            #pragma unroll
            for (int jj = 0; jj < 2; ++jj)
                #pragma unroll
                for (int p = 0; p < 4; ++p) { accR[jj][p] = 0ull; accZ[jj][p] = 0ull; accN[jj][p] = 0ull; }

            #pragma unroll 4
            for (int k = 0; k < HH; ++k) {
                const float* hrow = hc + k * HT_S + bloc;
                unsigned long long hv[4];
                #pragma unroll
                for (int p = 0; p < 4; ++p) hv[p] = *(const unsigned long long*)(hrow + 2 * p);
                const float* wrow = wT + k * WT_S + j0;
                const float2 wr = *(const float2*)(wrow);
                const float2 wz = *(const float2*)(wrow + 64);
                const float2 wn = *(const float2*)(wrow + 128);
                const unsigned long long wr0 = dup2(wr.x), wr1 = dup2(wr.y);
                const unsigned long long wz0 = dup2(wz.x), wz1 = dup2(wz.y);
                const unsigned long long wn0 = dup2(wn.x), wn1 = dup2(wn.y);
                #pragma unroll
                for (int p = 0; p < 4; ++p) {
                    accR[0][p] = ffma2(wr0, hv[p], accR[0][p]);
                    accR[1][p] = ffma2(wr1, hv[p], accR[1][p]);
                    accZ[0][p] = ffma2(wz0, hv[p], accZ[0][p]);
                    accZ[1][p] = ffma2(wz1, hv[p], accZ[1][p]);
                    accN[0][p] = ffma2(wn0, hv[p], accN[0][p]);
                    accN[1][p] = ffma2(wn1, hv[p], accN[1][p]);
                }
            }

            const size_t gb = gbase0 + (size_t)t * HH;
            #pragma unroll
            for (int p = 0; p < 4; ++p) {
                const float2 xv = *(const float2*)&sxc[tl * 32 + bloc + 2 * p];
                const float2 aR0 = u2f(accR[0][p]), aR1 = u2f(accR[1][p]);
                const float2 aZ0 = u2f(accZ[0][p]), aZ1 = u2f(accZ[1][p]);
                const float2 aN0 = u2f(accN[0][p]), aN1 = u2f(accN[1][p]);

                // j0, lane x (batch 2p) / lane y (batch 2p+1)
                const float r00 = fmaf(0.5f, tanh_ap(fmaf(xv.x, wir0, aR0.x + br0)), 0.5f);
                const float r0y = fmaf(0.5f, tanh_ap(fmaf(xv.y, wir0, aR0.y + br0)), 0.5f);
                const float z00 = fmaf(0.5f, tanh_ap(fmaf(xv.x, wiz0, aZ0.x + bz0)), 0.5f);
                const float z0y = fmaf(0.5f, tanh_ap(fmaf(xv.y, wiz0, aZ0.y + bz0)), 0.5f);
                const float n00 = tanh_ap(fmaf(xv.x, win0, fmaf(r00, aN0.x + bh0, bn0)));
                const float n0y = tanh_ap(fmaf(xv.y, win0, fmaf(r0y, aN0.y + bh0, bn0)));
                const float h00 = fmaf(z00, hp[0][p].x - n00, n00);
                const float h0y = fmaf(z0y, hp[0][p].y - n0y, n0y);
                // j0+1
                const float r10 = fmaf(0.5f, tanh_ap(fmaf(xv.x, wir1, aR1.x + br1)), 0.5f);
                const float r1y = fmaf(0.5f, tanh_ap(fmaf(xv.y, wir1, aR1.y + br1)), 0.5f);
                const float z10 = fmaf(0.5f, tanh_ap(fmaf(xv.x, wiz1, aZ1.x + bz1)), 0.5f);
                const float z1y = fmaf(0.5f, tanh_ap(fmaf(xv.y, wiz1, aZ1.y + bz1)), 0.5f);
                const float n10 = tanh_ap(fmaf(xv.x, win1, fmaf(r10, aN1.x + bh1, bn1)));
                const float n1y = tanh_ap(fmaf(xv.y, win1, fmaf(r1y, aN1.y + bh1, bn1)));
                const float h10 = fmaf(z10, hp[1][p].x - n10, n10);
                const float h1y = fmaf(z1y, hp[1][p].y - n1y, n1y);

                hp[0][p] = make_float2(h00, h0y);
                hp[1][p] = make_float2(h10, h1y);

                *(float2*)&hn[j0 * HT_S + bloc + 2 * p] = make_float2(h00, h0y);
                *(float2*)&hn[(j0 + 1) * HT_S + bloc + 2 * p] = make_float2(h10, h1y);
                *(float2*)&g_hs[gb + (size_t)(2 * p) * TT * HH] = make_float2(h00, h10);
                *(float2*)&g_hs[gb + (size_t)(2 * p + 1) * TT * HH] = make_float2(h0y, h1y);
            }
            __syncthreads();   // hn complete before next k-loop; sxc safe to reload
        }
    }
}

// =====================================================================
// Kernel B: per-(f,b) time attention (SingleAttention 'new', time-aware).
// grid (B, F), block 128.
// =====================================================================
__global__ void __launch_bounds__(128) attn_kernel(
    const float* __restrict__ att_Wt,   // (F,H,AH)
    const float* __restrict__ att_Wx,   // (F,H,AH)
    const float* __restrict__ att_rate) // (F,)
{
    __shared__ float sh[TT * 65];
    __shared__ float sWt[HH * AH];
    __shared__ float sWx[HH * AH];
    __shared__ float sq[AH];
    __shared__ float sa[TT];
    __shared__ float red[4], red2[4];
    __shared__ float pare[TT];

    const int b = blockIdx.x, f = blockIdx.y;
    const int tid = threadIdx.x;

    const float4* hsrc4 = (const float4*)(g_hs + ((size_t)(f * BB + b)) * TT * HH);
    for (int idx = tid; idx < TT * HH / 4; idx += 128) {
        float4 v = hsrc4[idx];
        const int row = idx >> 4;
        float* d = &sh[row * 65 + ((idx & 15) << 2)];
        d[0] = v.x; d[1] = v.y; d[2] = v.z; d[3] = v.w;
    }
    for (int idx = tid; idx < HH * AH; idx += 128) {
        sWt[idx] = att_Wt[(size_t)f * HH * AH + idx];
        sWx[idx] = att_Wx[(size_t)f * HH * AH + idx];
    }
    __syncthreads();

    if (tid < AH) {
        float q = 0.f;
        for (int j = 0; j < HH; ++j) q += sh[(TT - 1) * 65 + j] * sWt[j * AH + tid];
        sq[tid] = q;
    }
    __syncthreads();

    const int t = tid;
    float kv[AH];
    #pragma unroll
    for (int a = 0; a < AH; ++a) kv[a] = 0.f;
    for (int j = 0; j < HH; ++j) {
        const float hv = sh[t * 65 + j];
        #pragma unroll
        for (int a = 0; a < AH; ++a) kv[a] += hv * sWx[j * AH + a];
    }
    float dp = 0.f;
    #pragma unroll
    for (int a = 0; a < AH; ++a) dp += sq[a] * kv[a];

    const float sig = sigmoidf_(dp);
    const float sr = sigmoidf_(att_rate[f]);
    const float decay = (float)(TT - t);
    const float denom = sr * (__logf(2.72f + (1.0f - sig)) * decay);
    float e = fmaxf(__fdividef(sig, denom), 0.0f);

    float mval = e;
    #pragma unroll
    for (int o = 16; o > 0; o >>= 1) mval = fmaxf(mval, __shfl_xor_sync(0xffffffffu, mval, o));
    if ((tid & 31) == 0) red[tid >> 5] = mval;
    __syncthreads();
    mval = fmaxf(fmaxf(red[0], red[1]), fmaxf(red[2], red[3]));
    float ex = __expf(e - mval);
    float s = ex;
    #pragma unroll
    for (int o = 16; o > 0; o >>= 1) s += __shfl_xor_sync(0xffffffffu, s, o);
    if ((tid & 31) == 0) red2[tid >> 5] = s;
    __syncthreads();
    s = red2[0] + red2[1] + red2[2] + red2[3];
    sa[t] = __fdividef(ex, s);
    __syncthreads();

    const int hidx = tid & 63, part = tid >> 6;
    float acc = 0.f;
    const int t0 = part * 64;
    for (int tt2 = t0; tt2 < t0 + 64; ++tt2) acc += sa[tt2] * sh[tt2 * 65 + hidx];
    pare[tid] = acc;
    __syncthreads();
    if (tid < 64)
        g_emb[((size_t)b * FF + f) * HH + tid] = pare[tid] + pare[tid + 64];
}

// =====================================================================
// Kernel C: per-batch MHA + FFN + FinalAttention + head. (unchanged)
// =====================================================================
#define BUFSZ 4864   // 76*64

__device__ __forceinline__ void gemm76s(const float* __restrict__ sIn,
                                        const float* __restrict__ sW,
                                        const float* __restrict__ gB,
                                        float* __restrict__ sOut,
                                        int tid, bool addTo, bool relu)
{
    const int j0 = (tid & 31) * 2;
    const int i0 = tid >> 5;           // 0..7, rows i0 + 8r
    float ax[10], ay[10];
    #pragma unroll
    for (int r = 0; r < 10; ++r) { ax[r] = 0.f; ay[r] = 0.f; }
    for (int k = 0; k < HH; ++k) {
        const float2 w = *(const float2*)&sW[k * 64 + j0];
        #pragma unroll
        for (int r = 0; r < 10; ++r) {
            const float s = sIn[(i0 + 8 * r) * 64 + k];
            ax[r] += s * w.x;
            ay[r] += s * w.y;
        }
    }
    float2 bj = make_float2(0.f, 0.f);
    if (gB) bj = *(const float2*)&gB[j0];
    #pragma unroll
    for (int r = 0; r < 10; ++r) {
        const int i = i0 + 8 * r;
        if (i < FF) {
            float vx = ax[r] + bj.x;
            float vy = ay[r] + bj.y;
            if (addTo) { vx += sOut[i * 64 + j0]; vy += sOut[i * 64 + j0 + 1]; }
            if (relu)  { vx = fmaxf(vx, 0.f);     vy = fmaxf(vy, 0.f); }
            sOut[i * 64 + j0] = vx;
            sOut[i * 64 + j0 + 1] = vy;
        }
    }
}

__device__ __forceinline__ void stageW(const float* __restrict__ g,
                                       float* __restrict__ s, int tid)
{
    const float4* g4 = (const float4*)g;
    float4* s4 = (float4*)s;
    for (int i = tid; i < 1024; i += 256) s4[i] = g4[i];
}

#define SMEM_C_FLOATS (4 * BUFSZ + 5888)

__global__ void __launch_bounds__(256) mix_kernel(
    const float* __restrict__ wq, const float* __restrict__ bq,
    const float* __restrict__ wk, const float* __restrict__ bk,
    const float* __restrict__ wv, const float* __restrict__ bv,
    const float* __restrict__ wo, const float* __restrict__ bo,
    const float* __restrict__ w1, const float* __restrict__ b1,
    const float* __restrict__ w2, const float* __restrict__ b2,
    const float* __restrict__ fwq, const float* __restrict__ fbq,
    const float* __restrict__ fwk, const float* __restrict__ fbk,
    const float* __restrict__ fwv, const float* __restrict__ fbv,
    const float* __restrict__ o0w, const float* __restrict__ o0b,
    const float* __restrict__ o1w, const float* __restrict__ o1b,
    float* __restrict__ out)
{
    extern __shared__ float sm[];
    float* sE = sm;
    float* sQ = sE + BUFSZ;
    float* sK = sQ + BUFSZ;
    float* sV = sK + BUFSZ;
    float* sS = sV + BUFSZ;

    const int tid = threadIdx.x;
    const int b = blockIdx.x;

    {
        const float4* esrc = (const float4*)(g_emb + (size_t)b * FF * HH);
        float4* d4 = (float4*)sE;
        for (int idx = tid; idx < FF * HH / 4; idx += 256) d4[idx] = esrc[idx];
    }
    __syncthreads();

    stageW(wq, sS, tid); __syncthreads();
    gemm76s(sE, sS, bq, sQ, tid, false, false); __syncthreads();
    stageW(wk, sS, tid); __syncthreads();
    gemm76s(sE, sS, bk, sK, tid, false, false); __syncthreads();
    stageW(wv, sS, tid); __syncthreads();
    gemm76s(sE, sS, bv, sV, tid, false, false); __syncthreads();

    for (int h = 0; h < NHEAD; ++h) {
        const int hd = h * 16;
        for (int idx = tid; idx < FF * FF; idx += 256) {
            const int i = idx / FF, jf = idx % FF;
            float acc = 0.f;
            #pragma unroll
            for (int d = 0; d < 16; ++d) acc += sQ[i * HH + hd + d] * sK[jf * HH + hd + d];
            sS[idx] = acc * 0.25f;
        }
        __syncthreads();
        if (tid < FF) {
            float m = -1e30f;
            for (int jf = 0; jf < FF; ++jf) m = fmaxf(m, sS[tid * FF + jf]);
            float s = 0.f;
            for (int jf = 0; jf < FF; ++jf) { float e = __expf(sS[tid * FF + jf] - m); sS[tid * FF + jf] = e; s += e; }
            const float inv = __fdividef(1.0f, s);
            for (int jf = 0; jf < FF; ++jf) sS[tid * FF + jf] *= inv;
        }
        __syncthreads();
        for (int idx = tid; idx < FF * 16; idx += 256) {
            const int i = idx / 16, d = idx % 16;
            float acc = 0.f;
            for (int jf = 0; jf < FF; ++jf) acc += sS[i * FF + jf] * sV[jf * HH + hd + d];
            sQ[i * HH + hd + d] = acc;
        }
        __syncthreads();
    }

    stageW(wo, sS, tid); __syncthreads();
    gemm76s(sQ, sS, bo, sE, tid, true, false); __syncthreads();

    for (int c = 0; c < 4; ++c) {
        for (int idx = tid; idx < 4096; idx += 256) {
            const int k = idx >> 6, j = idx & 63;
            sS[idx] = w1[k * DFF + 64 * c + j];
        }
        {
            const float4* g4 = (const float4*)(w2 + 4096 * c);
            float4* s4 = (float4*)sK;
            for (int i = tid; i < 1024; i += 256) s4[i] = g4[i];
        }
        __syncthreads();
        gemm76s(sE, sS, b1 + 64 * c, sQ, tid, false, true);
        __syncthreads();
        gemm76s(sQ, sK, (c == 0) ? b2 : nullptr, sV, tid, c > 0, false);
        __syncthreads();
    }
    for (int idx = tid; idx < FF * HH; idx += 256) sE[idx] += sV[idx];
    __syncthreads();

    float* fqS = sS + 4608;
    float* feS = sS + 4672;
    float* wS  = sS + 4768;
    float* vS  = sS + 4848;
    float* uS  = sS + 4912;
    float* msS = sS + 4976;

    if (tid < HH) {
        float acc = fbq[tid];
        for (int k = 0; k < HH; ++k) acc += sE[(FF - 1) * HH + k] * fwq[k * HH + tid];
        fqS[tid] = acc;
    }
    stageW(fwk, sS, tid); __syncthreads();
    gemm76s(sE, sS, fbk, sQ, tid, false, false); __syncthreads();
    stageW(fwv, sS, tid); __syncthreads();
    gemm76s(sE, sS, fbv, sK, tid, false, false); __syncthreads();

    if (tid < FF) {
        float acc = 0.f;
        for (int j = 0; j < HH; ++j) acc += sQ[tid * HH + j] * fqS[j];
        feS[tid] = acc;
    }
    __syncthreads();
    if (tid == 0) {
        float m = -1e30f;
        for (int i = 0; i < FF; ++i) m = fmaxf(m, feS[i]);
        float s = 0.f;
        for (int i = 0; i < FF; ++i) { float e = __expf(feS[i] - m); wS[i] = e; s += e; }
        msS[0] = __fdividef(1.0f, s);
    }
    __syncthreads();
    const float inv = msS[0];
    if (tid < HH) {
        float acc = 0.f;
        for (int i = 0; i < FF; ++i) acc += (wS[i] * inv) * sK[i * HH + tid];
        vS[tid] = acc;
    }
    __syncthreads();
    if (tid < HH) {
        float acc = o0b[tid];
        for (int k = 0; k < HH; ++k) acc += vS[k] * o0w[k * HH + tid];
        uS[tid] = fmaxf(acc, 0.0f);
    }
    __syncthreads();
    if (tid == 0) {
        float acc = o1b[0];
        for (int j = 0; j < HH; ++j) acc += uS[j] * o1w[j];
        out[b] = sigmoidf_(acc);
    }
}

// =====================================================================
extern "C" void kernel_launch(void* const* d_in, const int* in_sizes, int n_in,
                              void* d_out, int out_size)
{
    const float* x     = (const float*)d_in[0];
    const float* wih   = (const float*)d_in[1];
    const float* whh   = (const float*)d_in[2];
    const float* bih   = (const float*)d_in[3];
    const float* bhh   = (const float*)d_in[4];
    const float* aWt   = (const float*)d_in[5];
    const float* aWx   = (const float*)d_in[6];
    const float* arate = (const float*)d_in[7];
    const float* mwq = (const float*)d_in[8],  *mbq = (const float*)d_in[9];
    const float* mwk = (const float*)d_in[10], *mbk = (const float*)d_in[11];
    const float* mwv = (const float*)d_in[12], *mbv = (const float*)d_in[13];
    const float* mwo = (const float*)d_in[14], *mbo = (const float*)d_in[15];
    const float* fw1 = (const float*)d_in[16], *fb1 = (const float*)d_in[17];
    const float* fw2 = (const float*)d_in[18], *fb2 = (const float*)d_in[19];
    const float* fwq = (const float*)d_in[20], *fbq = (const float*)d_in[21];
    const float* fwk = (const float*)d_in[22], *fbk = (const float*)d_in[23];
    const float* fwv = (const float*)d_in[24], *fbv = (const float*)d_in[25];
    const float* o0w = (const float*)d_in[26], *o0b = (const float*)d_in[27];
    const float* o1w = (const float*)d_in[28], *o1b = (const float*)d_in[29];
    float* out = (float*)d_out;

    const int smemA = SMEM_A_FLOATS * 4;
    const int smemC = SMEM_C_FLOATS * 4;
    cudaFuncSetAttribute(gru_kernel, cudaFuncAttributeMaxDynamicSharedMemorySize, smemA);
    cudaFuncSetAttribute(mix_kernel, cudaFuncAttributeMaxDynamicSharedMemorySize, smemC);

    gru_kernel<<<dim3(BB / 32, FF), 128, smemA>>>(x, wih, whh, bih, bhh);
    attn_kernel<<<dim3(BB, FF), 128>>>(aWt, aWx, arate);
    mix_kernel<<<BB, 256, smemC>>>(mwq, mbq, mwk, mbk, mwv, mbv, mwo, mbo,
                                   fw1, fb1, fw2, fb2,
                                   fwq, fbq, fwk, fbk, fwv, fbv,
                                   o0w, o0b, o1w, o1b, out);
}